// round 3
// baseline (speedup 1.0000x reference)
#include <cuda_runtime.h>

#define NCAM 6
#define C    64
#define HF   64
#define WF   176
#define NY   4
#define ZD   129
#define XD   129
#define NH   3
#define DD   128
#define WDIM 128

// Scratch (static device globals: allocation-free per harness rules)
__device__ float  g_integ[NCAM * HF * WF * C];   // [n][h][w][c]  (17.3 MB)
__device__ float2 g_nc[NCAM * NY * ZD * XD];     // [n][ny][zi][xi] (3.2 MB)

// ---------------------------------------------------------------------------
// Kernel 1: integral image per (n,c), transposed to channels-last [n][h][w][c]
// ---------------------------------------------------------------------------
__global__ void __launch_bounds__(256) integral_kernel(const float* __restrict__ feat) {
    __shared__ float tile[HF * WF];              // 45056 B
    const int ncid = blockIdx.x;                 // n*C + c
    const int n = ncid / C, c = ncid % C;
    const int tid = threadIdx.x;

    const float* src = feat + (size_t)ncid * HF * WF;
    for (int i = tid; i < HF * WF; i += 256) tile[i] = src[i];
    __syncthreads();

    // Row-wise inclusive scan: 8 warps, warp wp handles rows wp, wp+8, ...
    const int lane = tid & 31, wp = tid >> 5;
    for (int row = wp; row < HF; row += 8) {
        float carry = 0.f;
        #pragma unroll
        for (int seg = 0; seg < 6; seg++) {
            int w = seg * 32 + lane;
            float v = (w < WF) ? tile[row * WF + w] : 0.f;
            #pragma unroll
            for (int off = 1; off < 32; off <<= 1) {
                float u = __shfl_up_sync(0xffffffffu, v, off);
                if (lane >= off) v += u;
            }
            v += carry;
            if (w < WF) tile[row * WF + w] = v;
            carry = __shfl_sync(0xffffffffu, v, 31);
        }
    }
    __syncthreads();

    // Column-wise scan (serial over H, thread per column)
    if (tid < WF) {
        float acc = 0.f;
        for (int h = 0; h < HF; h++) {
            acc += tile[h * WF + tid];
            tile[h * WF + tid] = acc;
        }
    }
    __syncthreads();

    // Write channels-last
    float* dst = g_integ + (size_t)n * HF * WF * C + c;
    for (int i = tid; i < HF * WF; i += 256) dst[(size_t)i * C] = tile[i];
}

// ---------------------------------------------------------------------------
// Kernel 2: project all grid corners to clipped normalized coords g_nc
// ---------------------------------------------------------------------------
__global__ void proj_kernel(const float* __restrict__ ks,
                            const float* __restrict__ m2c,
                            const float* __restrict__ prot,
                            const float* __restrict__ ptran,
                            const float* __restrict__ und,
                            const float* __restrict__ grid) {
    const int id = blockIdx.x * blockDim.x + threadIdx.x;
    const int total = NCAM * NY * ZD * XD;
    if (id >= total) return;
    const int xi = id % XD;
    const int zi = (id / XD) % ZD;
    const int ny = (id / (XD * ZD)) % NY;
    const int n  = id / (XD * ZD * NY);

    const float* K  = ks    + n * 9;
    const float* M  = m2c   + n * 12;
    const float* PR = prot  + n * 9;
    const float* PT = ptran + n * 3;
    const float* Dd = und   + n * 7;

    float cal[3][4];
    #pragma unroll
    for (int i = 0; i < 3; i++)
        #pragma unroll
        for (int j = 0; j < 4; j++)
            cal[i][j] = K[i*3+0]*M[0*4+j] + K[i*3+1]*M[1*4+j] + K[i*3+2]*M[2*4+j];

    const float* g = grid + ((size_t)zi * XD + xi) * 3;
    const float vx = g[0];
    const float vy = g[1] + (2.0f - (float)ny);   // ys = -arange(0,4)+2
    const float vz = g[2];

    float hx = cal[0][0]*vx + cal[0][1]*vy + cal[0][2]*vz + cal[0][3];
    float hy = cal[1][0]*vx + cal[1][1]*vy + cal[1][2]*vz + cal[1][3];
    float hz = cal[2][0]*vx + cal[2][1]*vy + cal[2][2]*vz + cal[2][3];

    const float posf = (hz > 0.f) ? 1.f : 0.f;
    hx *= posf; hy *= posf;
    const float px = hx / hz, py = hy / hz;

    const float cx = K[2], cy = K[5], fx = K[0], fy = K[4];
    const float x = (px - cx) / fx, y = (py - cy) / fy;

    float xd, yd;
    if (Dd[6] == 1.0f) {  // fisheye
        float r  = sqrtf(x*x + y*y);
        float th = atanf(r);
        float t2 = th * th;
        float t4 = t2 * t2;
        float rad = th * (1.f + Dd[0]*t2 + Dd[1]*t4 + Dd[2]*t4*t2 + Dd[5]*t4*t4) / r;
        xd = x * rad * fx + cx;
        yd = y * rad * fy + cy;
    } else {              // pinhole
        float r2 = x*x + y*y;
        float r4 = r2 * r2;
        float poly = 1.f + Dd[0]*r2 + Dd[1]*r4 + Dd[2]*r4*r2;
        float p1 = Dd[3], p2 = Dd[4];
        float xdd = x*poly + (2.f*p1*x*y + p2*(r2 + 2.f*x*x));
        float ydd = y*poly + (p1*(r2 + 2.f*y*y) + 2.f*p2*x*y);
        xd = xdd * fx + cx;
        yd = ydd * fy + cy;
    }
    xd *= posf; yd *= posf;

    const float qx = PR[0]*xd + PR[1]*yd + PT[0];
    const float qy = PR[3]*xd + PR[4]*yd + PT[1];

    float2 o;
    o.x = fminf(fmaxf(2.f*qx - 1.f, -1.f), 1.f);
    o.y = fminf(fmaxf(2.f*qy - 1.f, -1.f), 1.f);
    g_nc[id] = o;
}

// ---------------------------------------------------------------------------
// Kernel 3: per voxel — bbox from 8 corners, 4 bilinear samples of integral
// image (channels-last, coalesced float2 per thread), max over cameras.
// Block: 32 x 8 (threadIdx.x = channel-pair, threadIdx.y = voxel in 8-run).
// ---------------------------------------------------------------------------
__global__ void __launch_bounds__(256) vox_kernel(float* __restrict__ out) {
    const int nhd = blockIdx.x >> 4;             // 16 blocks per (nh,d) row
    const int d   = nhd & 127;
    const int nh  = nhd >> 7;
    const int wd0 = (blockIdx.x & 15) << 3;
    const int wd  = wd0 + threadIdx.y;
    const int t   = threadIdx.x;                 // channels 2t, 2t+1

    float m0 = -3.402823466e38f, m1 = -3.402823466e38f;

    #pragma unroll 1
    for (int n = 0; n < NCAM; n++) {
        const float2* ncp = g_nc + n * (NY * ZD * XD) + ((size_t)nh * ZD + d) * XD + wd;

        float l = 1e30f, r = -1e30f, tp = 1e30f, bt = -1e30f;
        #pragma unroll
        for (int a = 0; a < 2; a++)
            #pragma unroll
            for (int b = 0; b < 2; b++)
                #pragma unroll
                for (int cc = 0; cc < 2; cc++) {
                    float2 p = __ldg(ncp + (a * ZD + b) * XD + cc);
                    l  = fminf(l,  p.x); r  = fmaxf(r,  p.x);
                    tp = fminf(tp, p.y); bt = fmaxf(bt, p.y);
                }

        const float area = (r - l) * (bt - tp) * (HF * WF * 0.25f) + 1e-6f;
        if (!(area > 1e-6f)) {                   // masked: candidate is exact 0
            m0 = fmaxf(m0, 0.f);
            m1 = fmaxf(m1, 0.f);
            continue;
        }

        // grid_sample(align_corners=True, border): [-1,1] -> [0, dim-1]
        float pxl = fminf(fmaxf((l  + 1.f) * 87.5f, 0.f), 175.f);
        float pxr = fminf(fmaxf((r  + 1.f) * 87.5f, 0.f), 175.f);
        float pyt = fminf(fmaxf((tp + 1.f) * 31.5f, 0.f), 63.f);
        float pyb = fminf(fmaxf((bt + 1.f) * 31.5f, 0.f), 63.f);

        float fxl = floorf(pxl), fxr = floorf(pxr);
        float fyt = floorf(pyt), fyb = floorf(pyb);
        float wx[2] = {pxl - fxl, pxr - fxr};
        float wy[2] = {pyt - fyt, pyb - fyb};
        int x0[2] = {(int)fxl, (int)fxr};
        int y0[2] = {(int)fyt, (int)fyb};
        int x1[2] = {min(x0[0] + 1, WF - 1), min(x0[1] + 1, WF - 1)};
        int y1[2] = {min(y0[0] + 1, HF - 1), min(y0[1] + 1, HF - 1)};

        const float2* base = (const float2*)(g_integ + (size_t)n * HF * WF * C) + t;

        // 16 texel fetches (coalesced 256B per warp each), shared geometry
        float2 v[2][2][2][2];   // [yTB][y01][xLR][x01]
        #pragma unroll
        for (int yt = 0; yt < 2; yt++) {
            int ya = y0[yt], yb2 = y1[yt];
            #pragma unroll
            for (int xl = 0; xl < 2; xl++) {
                int xa = x0[xl], xb = x1[xl];
                v[yt][0][xl][0] = __ldg(base + (ya  * WF + xa) * (C / 2));
                v[yt][0][xl][1] = __ldg(base + (ya  * WF + xb) * (C / 2));
                v[yt][1][xl][0] = __ldg(base + (yb2 * WF + xa) * (C / 2));
                v[yt][1][xl][1] = __ldg(base + (yb2 * WF + xb) * (C / 2));
            }
        }

        float2 samp[2][2];      // [yTB][xLR]
        #pragma unroll
        for (int yt = 0; yt < 2; yt++) {
            float wyv = wy[yt];
            #pragma unroll
            for (int xl = 0; xl < 2; xl++) {
                float wxv = wx[xl];
                float r0x = v[yt][0][xl][0].x * (1.f - wxv) + v[yt][0][xl][1].x * wxv;
                float r0y = v[yt][0][xl][0].y * (1.f - wxv) + v[yt][0][xl][1].y * wxv;
                float r1x = v[yt][1][xl][0].x * (1.f - wxv) + v[yt][1][xl][1].x * wxv;
                float r1y = v[yt][1][xl][0].y * (1.f - wxv) + v[yt][1][xl][1].y * wxv;
                samp[yt][xl].x = r0x * (1.f - wyv) + r1x * wyv;
                samp[yt][xl].y = r0y * (1.f - wyv) + r1y * wyv;
            }
        }
        // tl + br - tr - bl
        float nx = samp[0][0].x + samp[1][1].x - samp[0][1].x - samp[1][0].x;
        float nyv = samp[0][0].y + samp[1][1].y - samp[0][1].y - samp[1][0].y;
        m0 = fmaxf(m0, nx / area);
        m1 = fmaxf(m1, nyv / area);
    }

    // Stage results in smem, write coalesced 32B segments:
    // out[((c*NH + nh)*DD + d)*WDIM + wd]
    __shared__ float res[C * 9];                 // padded rows of 9
    res[(2 * t    ) * 9 + threadIdx.y] = m0;
    res[(2 * t + 1) * 9 + threadIdx.y] = m1;
    __syncthreads();

    const int i = threadIdx.y * 32 + threadIdx.x;   // 0..255
    #pragma unroll
    for (int rep = 0; rep < 2; rep++) {
        int idx = i + rep * 256;                 // 0..511 = c*8 + j
        int ch  = idx >> 3;
        int j   = idx & 7;
        out[((size_t)(ch * NH + nh) * DD + d) * WDIM + wd0 + j] = res[ch * 9 + j];
    }
}

// ---------------------------------------------------------------------------
extern "C" void kernel_launch(void* const* d_in, const int* in_sizes, int n_in,
                              void* d_out, int out_size) {
    (void)in_sizes; (void)n_in; (void)out_size;
    const float* features  = (const float*)d_in[0];  // [1,6,64,64,176]
    const float* ks        = (const float*)d_in[1];  // [1,6,3,3]
    const float* imu2cs    = (const float*)d_in[2];  // [1,6,3,4]
    const float* post_rots = (const float*)d_in[3];  // [1,6,3,3]
    const float* post_trans= (const float*)d_in[4];  // [1,6,3]
    const float* undists   = (const float*)d_in[5];  // [1,6,7]
    const float* grid      = (const float*)d_in[6];  // [1,129,129,3]
    float* out = (float*)d_out;                      // [1,192,128,128]

    integral_kernel<<<NCAM * C, 256>>>(features);

    const int totalP = NCAM * NY * ZD * XD;
    proj_kernel<<<(totalP + 255) / 256, 256>>>(ks, imu2cs, post_rots, post_trans,
                                               undists, grid);

    dim3 blk(32, 8);
    vox_kernel<<<(NH * DD * WDIM) / 8, blk>>>(out);
}

// round 5
// speedup vs baseline: 1.9722x; 1.9722x over previous
#include <cuda_runtime.h>

#define NCAM 6
#define C    64
#define HF   64
#define WF   176
#define NY   4
#define ZD   129
#define XD   129
#define NH   3
#define DD   128
#define WDIM 128

// Scratch (static device globals: allocation-free per harness rules)
__device__ float  g_tmpi[NCAM * C * HF * WF];    // [n][c][h][w]  channel-major integral
__device__ float  g_integ[NCAM * HF * WF * C];   // [n][h][w][c]  channels-last integral
__device__ float2 g_nc[NCAM * NY * ZD * XD];     // [n][ny][zi][xi]

// ---------------------------------------------------------------------------
// Kernel 1: integral image per (n,c), COALESCED write to channel-major scratch
// ---------------------------------------------------------------------------
__global__ void __launch_bounds__(256) integral_kernel(const float* __restrict__ feat) {
    __shared__ float tile[HF * WF];              // 45056 B
    const int ncid = blockIdx.x;                 // n*C + c
    const int tid = threadIdx.x;

    const float* src = feat + (size_t)ncid * HF * WF;
    for (int i = tid; i < HF * WF; i += 256) tile[i] = src[i];
    __syncthreads();

    // Row-wise inclusive scan: 8 warps, warp wp handles rows wp, wp+8, ...
    const int lane = tid & 31, wp = tid >> 5;
    for (int row = wp; row < HF; row += 8) {
        float carry = 0.f;
        #pragma unroll
        for (int seg = 0; seg < 6; seg++) {
            int w = seg * 32 + lane;
            float v = (w < WF) ? tile[row * WF + w] : 0.f;
            #pragma unroll
            for (int off = 1; off < 32; off <<= 1) {
                float u = __shfl_up_sync(0xffffffffu, v, off);
                if (lane >= off) v += u;
            }
            v += carry;
            if (w < WF) tile[row * WF + w] = v;
            carry = __shfl_sync(0xffffffffu, v, 31);
        }
    }
    __syncthreads();

    // Column-wise scan (serial over H, thread per column)
    if (tid < WF) {
        float acc = 0.f;
        #pragma unroll 4
        for (int h = 0; h < HF; h++) {
            acc += tile[h * WF + tid];
            tile[h * WF + tid] = acc;
        }
    }
    __syncthreads();

    // Coalesced channel-major write
    float* dst = g_tmpi + (size_t)ncid * HF * WF;
    for (int i = tid; i < HF * WF; i += 256) dst[i] = tile[i];
}

// ---------------------------------------------------------------------------
// Kernel 1b: transpose [n][c][h][w] -> [n][h][w][c], smem tile, both sides
// coalesced, stride-33 padding for bank-conflict-free access.
// Grid: (ceil(WF/32)=6, HF, NCAM), block 256.
// ---------------------------------------------------------------------------
__global__ void __launch_bounds__(256) transpose_kernel() {
    __shared__ float tile[C * 33];               // [c][w] padded, 8448 B
    const int n  = blockIdx.z;
    const int h  = blockIdx.y;
    const int w0 = blockIdx.x * 32;

    const float* src = g_tmpi + ((size_t)n * C * HF + h) * WF;
    for (int idx = threadIdx.x; idx < C * 32; idx += 256) {
        int c = idx >> 5, w = idx & 31;
        int gw = w0 + w;
        tile[c * 33 + w] = (gw < WF) ? src[(size_t)c * HF * WF + gw] : 0.f;
    }
    __syncthreads();

    float* dst = g_integ + (((size_t)n * HF + h) * WF) * C;
    for (int idx = threadIdx.x; idx < C * 32; idx += 256) {
        int w = idx >> 6, c = idx & 63;          // c fast -> coalesced 128B
        int gw = w0 + w;
        if (gw < WF) dst[(size_t)gw * C + c] = tile[c * 33 + w];
    }
}

// ---------------------------------------------------------------------------
// Kernel 2: project all grid corners to clipped normalized coords g_nc
// ---------------------------------------------------------------------------
__global__ void proj_kernel(const float* __restrict__ ks,
                            const float* __restrict__ m2c,
                            const float* __restrict__ prot,
                            const float* __restrict__ ptran,
                            const float* __restrict__ und,
                            const float* __restrict__ grid) {
    const int id = blockIdx.x * blockDim.x + threadIdx.x;
    const int total = NCAM * NY * ZD * XD;
    if (id >= total) return;
    const int xi = id % XD;
    const int zi = (id / XD) % ZD;
    const int ny = (id / (XD * ZD)) % NY;
    const int n  = id / (XD * ZD * NY);

    const float* K  = ks    + n * 9;
    const float* M  = m2c   + n * 12;
    const float* PR = prot  + n * 9;
    const float* PT = ptran + n * 3;
    const float* Dd = und   + n * 7;

    float cal[3][4];
    #pragma unroll
    for (int i = 0; i < 3; i++)
        #pragma unroll
        for (int j = 0; j < 4; j++)
            cal[i][j] = K[i*3+0]*M[0*4+j] + K[i*3+1]*M[1*4+j] + K[i*3+2]*M[2*4+j];

    const float* g = grid + ((size_t)zi * XD + xi) * 3;
    const float vx = g[0];
    const float vy = g[1] + (2.0f - (float)ny);   // ys = -arange(0,4)+2
    const float vz = g[2];

    float hx = cal[0][0]*vx + cal[0][1]*vy + cal[0][2]*vz + cal[0][3];
    float hy = cal[1][0]*vx + cal[1][1]*vy + cal[1][2]*vz + cal[1][3];
    float hz = cal[2][0]*vx + cal[2][1]*vy + cal[2][2]*vz + cal[2][3];

    const float posf = (hz > 0.f) ? 1.f : 0.f;
    hx *= posf; hy *= posf;
    const float px = hx / hz, py = hy / hz;

    const float cx = K[2], cy = K[5], fx = K[0], fy = K[4];
    const float x = (px - cx) / fx, y = (py - cy) / fy;

    float xd, yd;
    if (Dd[6] == 1.0f) {  // fisheye
        float r  = sqrtf(x*x + y*y);
        float th = atanf(r);
        float t2 = th * th;
        float t4 = t2 * t2;
        float rad = th * (1.f + Dd[0]*t2 + Dd[1]*t4 + Dd[2]*t4*t2 + Dd[5]*t4*t4) / r;
        xd = x * rad * fx + cx;
        yd = y * rad * fy + cy;
    } else {              // pinhole
        float r2 = x*x + y*y;
        float r4 = r2 * r2;
        float poly = 1.f + Dd[0]*r2 + Dd[1]*r4 + Dd[2]*r4*r2;
        float p1 = Dd[3], p2 = Dd[4];
        float xdd = x*poly + (2.f*p1*x*y + p2*(r2 + 2.f*x*x));
        float ydd = y*poly + (p1*(r2 + 2.f*y*y) + 2.f*p2*x*y);
        xd = xdd * fx + cx;
        yd = ydd * fy + cy;
    }
    xd *= posf; yd *= posf;

    const float qx = PR[0]*xd + PR[1]*yd + PT[0];
    const float qy = PR[3]*xd + PR[4]*yd + PT[1];

    float2 o;
    o.x = fminf(fmaxf(2.f*qx - 1.f, -1.f), 1.f);
    o.y = fminf(fmaxf(2.f*qy - 1.f, -1.f), 1.f);
    g_nc[id] = o;
}

// ---------------------------------------------------------------------------
// Kernel 3: per voxel — bbox from 8 corners, 4 bilinear samples of integral
// image (channels-last, coalesced float2 per thread), max over cameras.
// Block: 32 x 8 (threadIdx.x = channel-pair, threadIdx.y = voxel in 8-run).
// ---------------------------------------------------------------------------
__global__ void __launch_bounds__(256) vox_kernel(float* __restrict__ out) {
    const int nhd = blockIdx.x >> 4;             // 16 blocks per (nh,d) row
    const int d   = nhd & 127;
    const int nh  = nhd >> 7;
    const int wd0 = (blockIdx.x & 15) << 3;
    const int wd  = wd0 + threadIdx.y;
    const int t   = threadIdx.x;                 // channels 2t, 2t+1

    float m0 = -3.402823466e38f, m1 = -3.402823466e38f;

    #pragma unroll 1
    for (int n = 0; n < NCAM; n++) {
        const float2* ncp = g_nc + n * (NY * ZD * XD) + ((size_t)nh * ZD + d) * XD + wd;

        float l = 1e30f, r = -1e30f, tp = 1e30f, bt = -1e30f;
        #pragma unroll
        for (int a = 0; a < 2; a++)
            #pragma unroll
            for (int b = 0; b < 2; b++)
                #pragma unroll
                for (int cc = 0; cc < 2; cc++) {
                    float2 p = __ldg(ncp + (a * ZD + b) * XD + cc);
                    l  = fminf(l,  p.x); r  = fmaxf(r,  p.x);
                    tp = fminf(tp, p.y); bt = fmaxf(bt, p.y);
                }

        const float area = (r - l) * (bt - tp) * (HF * WF * 0.25f) + 1e-6f;
        if (!(area > 1e-6f)) {                   // masked: candidate is exact 0
            m0 = fmaxf(m0, 0.f);
            m1 = fmaxf(m1, 0.f);
            continue;
        }

        // grid_sample(align_corners=True, border): [-1,1] -> [0, dim-1]
        float pxl = fminf(fmaxf((l  + 1.f) * 87.5f, 0.f), 175.f);
        float pxr = fminf(fmaxf((r  + 1.f) * 87.5f, 0.f), 175.f);
        float pyt = fminf(fmaxf((tp + 1.f) * 31.5f, 0.f), 63.f);
        float pyb = fminf(fmaxf((bt + 1.f) * 31.5f, 0.f), 63.f);

        float fxl = floorf(pxl), fxr = floorf(pxr);
        float fyt = floorf(pyt), fyb = floorf(pyb);
        float wx[2] = {pxl - fxl, pxr - fxr};
        float wy[2] = {pyt - fyt, pyb - fyb};
        int x0[2] = {(int)fxl, (int)fxr};
        int y0[2] = {(int)fyt, (int)fyb};
        int x1[2] = {min(x0[0] + 1, WF - 1), min(x0[1] + 1, WF - 1)};
        int y1[2] = {min(y0[0] + 1, HF - 1), min(y0[1] + 1, HF - 1)};

        const float2* base = (const float2*)(g_integ + (size_t)n * HF * WF * C) + t;

        // 16 texel fetches (coalesced 256B per warp each), shared geometry
        float2 v[2][2][2][2];   // [yTB][y01][xLR][x01]
        #pragma unroll
        for (int yt = 0; yt < 2; yt++) {
            int ya = y0[yt], yb2 = y1[yt];
            #pragma unroll
            for (int xl = 0; xl < 2; xl++) {
                int xa = x0[xl], xb = x1[xl];
                v[yt][0][xl][0] = __ldg(base + (ya  * WF + xa) * (C / 2));
                v[yt][0][xl][1] = __ldg(base + (ya  * WF + xb) * (C / 2));
                v[yt][1][xl][0] = __ldg(base + (yb2 * WF + xa) * (C / 2));
                v[yt][1][xl][1] = __ldg(base + (yb2 * WF + xb) * (C / 2));
            }
        }

        float2 samp[2][2];      // [yTB][xLR]
        #pragma unroll
        for (int yt = 0; yt < 2; yt++) {
            float wyv = wy[yt];
            #pragma unroll
            for (int xl = 0; xl < 2; xl++) {
                float wxv = wx[xl];
                float r0x = v[yt][0][xl][0].x * (1.f - wxv) + v[yt][0][xl][1].x * wxv;
                float r0y = v[yt][0][xl][0].y * (1.f - wxv) + v[yt][0][xl][1].y * wxv;
                float r1x = v[yt][1][xl][0].x * (1.f - wxv) + v[yt][1][xl][1].x * wxv;
                float r1y = v[yt][1][xl][0].y * (1.f - wxv) + v[yt][1][xl][1].y * wxv;
                samp[yt][xl].x = r0x * (1.f - wyv) + r1x * wyv;
                samp[yt][xl].y = r0y * (1.f - wyv) + r1y * wyv;
            }
        }
        // tl + br - tr - bl
        float nx = samp[0][0].x + samp[1][1].x - samp[0][1].x - samp[1][0].x;
        float nyv = samp[0][0].y + samp[1][1].y - samp[0][1].y - samp[1][0].y;
        m0 = fmaxf(m0, nx / area);
        m1 = fmaxf(m1, nyv / area);
    }

    // Stage results in smem, write coalesced 32B segments:
    // out[((c*NH + nh)*DD + d)*WDIM + wd]
    __shared__ float res[C * 9];                 // padded rows of 9
    res[(2 * t    ) * 9 + threadIdx.y] = m0;
    res[(2 * t + 1) * 9 + threadIdx.y] = m1;
    __syncthreads();

    const int i = threadIdx.y * 32 + threadIdx.x;   // 0..255
    #pragma unroll
    for (int rep = 0; rep < 2; rep++) {
        int idx = i + rep * 256;                 // 0..511 = c*8 + j
        int ch  = idx >> 3;
        int j   = idx & 7;
        out[((size_t)(ch * NH + nh) * DD + d) * WDIM + wd0 + j] = res[ch * 9 + j];
    }
}

// ---------------------------------------------------------------------------
extern "C" void kernel_launch(void* const* d_in, const int* in_sizes, int n_in,
                              void* d_out, int out_size) {
    (void)in_sizes; (void)n_in; (void)out_size;
    const float* features  = (const float*)d_in[0];  // [1,6,64,64,176]
    const float* ks        = (const float*)d_in[1];  // [1,6,3,3]
    const float* imu2cs    = (const float*)d_in[2];  // [1,6,3,4]
    const float* post_rots = (const float*)d_in[3];  // [1,6,3,3]
    const float* post_trans= (const float*)d_in[4];  // [1,6,3]
    const float* undists   = (const float*)d_in[5];  // [1,6,7]
    const float* grid      = (const float*)d_in[6];  // [1,129,129,3]
    float* out = (float*)d_out;                      // [1,192,128,128]

    integral_kernel<<<NCAM * C, 256>>>(features);

    dim3 tgrid((WF + 31) / 32, HF, NCAM);            // 6 x 64 x 6
    transpose_kernel<<<tgrid, 256>>>();

    const int totalP = NCAM * NY * ZD * XD;
    proj_kernel<<<(totalP + 255) / 256, 256>>>(ks, imu2cs, post_rots, post_trans,
                                               undists, grid);

    dim3 blk(32, 8);
    vox_kernel<<<(NH * DD * WDIM) / 8, blk>>>(out);
}